// round 14
// baseline (speedup 1.0000x reference)
#include <cuda_runtime.h>
#include <cstdint>

typedef unsigned long long u64;

// ---------------------------------------------------------------------------
// Per-hidden-unit interleaved record: 12 ulonglong2 (192B) = j record then n:
//  L0=(bias, w0) L1=(w4, w6) L2=(a1, a2) L3=(a3, b1) L4=(b2, b3) L5=(w2', 0)
// a_i=(w_k+w_k')/2, b_i=(w_k-w_k')/2 over FLIP pairs (1,2),(3,5),(7,8).
// straight = base + SUM a*p + SUM b*q ; flipped = base + SUM a*p - SUM b*q.
// w2'/output biases pre-scaled by log2(e)  (exp2-domain accumulators).
// Mi6 cols 0..2: x(-1/0.7) x0.5 ; cols 4,5: x0.5 ; col 3: x1
// (dm rows are produced at 2x scale from the unhalved pq basis; the 0.5 is
//  folded here. All scale factors are exact powers of two.)
// Weights live in __constant__ (warp-uniform h index -> LDC broadcast on the
// constant port; LSU/L1tex carries only f traffic).
// ---------------------------------------------------------------------------
struct __align__(16) Params {
    ulonglong2 W[24][12];
    float2 Mi6[9][6];
    float  jb2, nb2x2;
    float  pad[2];
};
__device__   Params g_p;   // staging (written by prep_kernel)
__constant__ Params cP;    // kernel-visible copy (memcpy'd in-stream)

__global__ void prep_kernel(const float* __restrict__ jw1, const float* __restrict__ jb1,
                            const float* __restrict__ jw2, const float* __restrict__ jb2,
                            const float* __restrict__ nw1, const float* __restrict__ nb1,
                            const float* __restrict__ nw2, const float* __restrict__ nb2,
                            const float* __restrict__ M,   const float* __restrict__ Mi)
{
    (void)M;
    const float LOG2E = 1.4426950408889634f;
    int t = threadIdx.x;
    if (t < 24) {
        int h = t;
        float2* wj = reinterpret_cast<float2*>(&g_p.W[h][0]);
        float2* wn = reinterpret_cast<float2*>(&g_p.W[h][6]);
        const float* J = jw1 + h * 9;
        const float* Nw = nw1 + h * 9;
        float v;
        v = jb1[h];               wj[0]  = make_float2(v, v);
        v = J[0];                 wj[1]  = make_float2(v, v);
        v = J[4];                 wj[2]  = make_float2(v, v);
        v = J[6];                 wj[3]  = make_float2(v, v);
        v = 0.5f * (J[1] + J[2]); wj[4]  = make_float2(v, v);  // a1
        v = 0.5f * (J[3] + J[5]); wj[5]  = make_float2(v, v);  // a2
        v = 0.5f * (J[7] + J[8]); wj[6]  = make_float2(v, v);  // a3
        v = 0.5f * (J[1] - J[2]); wj[7]  = make_float2(v, v);  // b1
        v = 0.5f * (J[3] - J[5]); wj[8]  = make_float2(v, v);  // b2
        v = 0.5f * (J[7] - J[8]); wj[9]  = make_float2(v, v);  // b3
        v = jw2[h] * LOG2E;       wj[10] = make_float2(v, v);
        wj[11] = make_float2(0.f, 0.f);
        v = nb1[h];                 wn[0]  = make_float2(v, v);
        v = Nw[0];                  wn[1]  = make_float2(v, v);
        v = Nw[4];                  wn[2]  = make_float2(v, v);
        v = Nw[6];                  wn[3]  = make_float2(v, v);
        v = 0.5f * (Nw[1] + Nw[2]); wn[4]  = make_float2(v, v);
        v = 0.5f * (Nw[3] + Nw[5]); wn[5]  = make_float2(v, v);
        v = 0.5f * (Nw[7] + Nw[8]); wn[6]  = make_float2(v, v);
        v = 0.5f * (Nw[1] - Nw[2]); wn[7]  = make_float2(v, v);
        v = 0.5f * (Nw[3] - Nw[5]); wn[8]  = make_float2(v, v);
        v = 0.5f * (Nw[7] - Nw[8]); wn[9]  = make_float2(v, v);
        v = nw2[h] * LOG2E;         wn[10] = make_float2(v, v);
        wn[11] = make_float2(0.f, 0.f);
    }
    if (t < 9)
        for (int c = 0; c < 6; ++c) {
            float v = Mi[t * 9 + 3 + c];
            if (c < 3) v *= -1.0f / 0.7f;   // fold tau=0.7 relaxation scale
            if (c != 3) v *= 0.5f;          // fold 2x scale of dm rows
            g_p.Mi6[t][c] = make_float2(v, v);
        }
    if (t == 0) { g_p.jb2 = jb2[0] * LOG2E; g_p.nb2x2 = 2.0f * nb2[0] * LOG2E; }
}

// ---------------------------------------------------------------------------
// f32x2 packed helpers
// ---------------------------------------------------------------------------
__device__ __forceinline__ u64 pk2(float lo, float hi) {
    u64 r; asm("mov.b64 %0, {%1, %2};" : "=l"(r) : "f"(lo), "f"(hi)); return r;
}
__device__ __forceinline__ void upk2(u64 v, float& lo, float& hi) {
    asm("mov.b64 {%0, %1}, %2;" : "=f"(lo), "=f"(hi) : "l"(v));
}
__device__ __forceinline__ u64 ffma2(u64 a, u64 b, u64 c) {
    u64 d; asm("fma.rn.f32x2 %0, %1, %2, %3;" : "=l"(d) : "l"(a), "l"(b), "l"(c)); return d;
}
__device__ __forceinline__ u64 fmul2(u64 a, u64 b) {
    u64 d; asm("mul.rn.f32x2 %0, %1, %2;" : "=l"(d) : "l"(a), "l"(b)); return d;
}
__device__ __forceinline__ u64 fadd2(u64 a, u64 b) {
    u64 d; asm("add.rn.f32x2 %0, %1, %2;" : "=l"(d) : "l"(a), "l"(b)); return d;
}
__device__ __forceinline__ u64 fsub2(u64 a, u64 b) {
    u64 d; asm("sub.rn.f32x2 %0, %1, %2;" : "=l"(d) : "l"(a), "l"(b)); return d;
}
__device__ __forceinline__ float rcpa(float x) {
    float r; asm("rcp.approx.f32 %0, %1;" : "=f"(r) : "f"(x)); return r;
}
__device__ __forceinline__ float ex2a(float x) {
    float r; asm("ex2.approx.f32 %0, %1;" : "=f"(r) : "f"(x)); return r;
}
__device__ __forceinline__ u64 relu2(u64 x) {
    float a, b; upk2(x, a, b);
    return pk2(fmaxf(a, 0.0f), fmaxf(b, 0.0f));
}

#define NPAIR 4   // packed cell-pairs per thread (8 cells)
#define CELLS (NPAIR * 2)

// Sparse hardcoded moment transform -> m0, m4, m6 and FLIP-pair basis
// pq = {p1,q1,p2,q2,p3,q3}; all negations via sub.rn.f32x2 (no LOP).
__device__ __forceinline__ void moments(const u64 (&f)[9],
                                        u64& m0, u64& m4, u64& m6, u64* pq,
                                        u64 c_m2, u64 c_4, u64 c_m13)
{
    u64 s58 = fadd2(f[5], f[8]);
    u64 s67 = fadd2(f[6], f[7]);
    u64 d58 = fsub2(f[5], f[8]);
    u64 d67 = fsub2(f[6], f[7]);
    u64 t13 = fsub2(f[1], f[3]);
    u64 t24 = fsub2(f[2], f[4]);
    u64 s13 = fadd2(f[1], f[3]);
    u64 s24 = fadd2(f[2], f[4]);
    u64 u = fsub2(s58, s67);               // f5-f6-f7+f8
    u64 v = fadd2(d58, d67);               // f5+f6-f7-f8
    u64 Q = fadd2(s58, s67);
    u64 P = fadd2(s13, s24);
    m0 = fadd2(f[0], fadd2(P, Q));
    m4 = fsub2(d58, d67);                  // f5-f6+f7-f8
    m6 = ffma2(P, c_m2, ffma2(Q, c_4, f[0]));
    u64 m1 = fadd2(t13, u);
    u64 m2 = fadd2(t24, v);
    u64 m3 = ffma2(m0, c_m13, fadd2(s13, Q));
    u64 m5 = ffma2(m0, c_m13, fadd2(s24, Q));
    u64 m7 = ffma2(t13, c_m2, fmul2(u, c_4));
    u64 m8 = ffma2(t24, c_m2, fmul2(v, c_4));
    pq[0] = fadd2(m1, m2);
    pq[1] = fsub2(m1, m2);
    pq[2] = fadd2(m3, m5);
    pq[3] = fsub2(m3, m5);
    pq[4] = fadd2(m7, m8);
    pq[5] = fsub2(m7, m8);
}

__global__ __launch_bounds__(128, 4) void lbm_kernel(const float* __restrict__ f,
                                                     float* __restrict__ out,
                                                     int N, int ntile)
{
    const u64 c_m2  = pk2(-2.0f, -2.0f);
    const u64 c_4   = pk2(4.0f, 4.0f);
    const u64 c_m13 = pk2(-1.0f / 3.0f, -1.0f / 3.0f);
    const u64 c_two = pk2(2.0f, 2.0f);
    const int MASK[9] = {0x0D, 0x1D, 0x2D, 0x1D, 0x2D, 0x3F, 0x3F, 0x3F, 0x3F};

    // Persistent CTAs: one wave (grid = 148*4); loop over tiles.
    for (int tile = blockIdx.x; tile < ntile; tile += gridDim.x) {
        int idx = (tile * 128 + threadIdx.x) * CELLS;
        if (idx >= N) continue;

        // ---- load f, compute moment basis; f regs die here (reloaded later)
        u64 m0[NPAIR], m4[NPAIR], m6[NPAIR], pq[NPAIR][6];
        {
            u64 fv[NPAIR][9];
            #pragma unroll
            for (int i = 0; i < 9; ++i) {
                float4 v0 = *reinterpret_cast<const float4*>(f + i * N + idx);
                float4 v1 = *reinterpret_cast<const float4*>(f + i * N + idx + 4);
                fv[0][i] = pk2(v0.x, v0.y);
                fv[1][i] = pk2(v0.z, v0.w);
                fv[2][i] = pk2(v1.x, v1.y);
                fv[3][i] = pk2(v1.z, v1.w);
            }
            #pragma unroll
            for (int p = 0; p < NPAIR; ++p)
                moments(fv[p], m0[p], m4[p], m6[p], pq[p], c_m2, c_4, c_m13);
        }

        // ---- fused j+n MLPs over 24 hidden units, weights via constant port
        u64 jx[NPAIR], jy[NPAIR], nn[NPAIR];
        {
            u64 jb = pk2(cP.jb2, cP.jb2);
            u64 nb = pk2(cP.nb2x2, cP.nb2x2);
            #pragma unroll
            for (int p = 0; p < NPAIR; ++p) { jx[p] = jb; jy[p] = jb; nn[p] = nb; }
        }

        for (int h = 0; h < 24; ++h) {
            // ---- j network
            {
                ulonglong2 L0 = cP.W[h][0], L1 = cP.W[h][1], L2 = cP.W[h][2];
                ulonglong2 L3 = cP.W[h][3], L4 = cP.W[h][4], L5 = cP.W[h][5];
                #pragma unroll
                for (int p = 0; p < NPAIR; ++p) {
                    u64 t = ffma2(L0.y, m0[p], L0.x);
                    t = ffma2(L1.x, m4[p], t);
                    t = ffma2(L1.y, m6[p], t);
                    t = ffma2(L2.x, pq[p][0], t);
                    t = ffma2(L2.y, pq[p][2], t);
                    t = ffma2(L3.x, pq[p][4], t);
                    u64 u = fmul2(L3.y, pq[p][1]);
                    u = ffma2(L4.x, pq[p][3], u);
                    u = ffma2(L4.y, pq[p][5], u);
                    u64 s = fadd2(t, u);
                    u64 fl = fsub2(t, u);
                    jx[p] = ffma2(L5.x, relu2(s), jx[p]);
                    jy[p] = ffma2(L5.x, relu2(fl), jy[p]);
                }
            }
            // ---- n network
            {
                ulonglong2 L0 = cP.W[h][6], L1 = cP.W[h][7], L2 = cP.W[h][8];
                ulonglong2 L3 = cP.W[h][9], L4 = cP.W[h][10], L5 = cP.W[h][11];
                #pragma unroll
                for (int p = 0; p < NPAIR; ++p) {
                    u64 t = ffma2(L0.y, m0[p], L0.x);
                    t = ffma2(L1.x, m4[p], t);
                    t = ffma2(L1.y, m6[p], t);
                    t = ffma2(L2.x, pq[p][0], t);
                    t = ffma2(L2.y, pq[p][2], t);
                    t = ffma2(L3.x, pq[p][4], t);
                    u64 u = fmul2(L3.y, pq[p][1]);
                    u = ffma2(L4.x, pq[p][3], u);
                    u = ffma2(L4.y, pq[p][5], u);
                    u64 s = fadd2(t, u);
                    u64 fl = fsub2(t, u);
                    nn[p] = ffma2(L5.x, fadd2(relu2(s), relu2(fl)), nn[p]);
                }
            }
        }

        // ---- per-pair relax factors and dm rows (2x scale; 0.5 folded in Mi6)
        u64 dm[NPAIR][6];
        #pragma unroll
        for (int p = 0; p < NPAIR; ++p) {
            float n0, n1, x0, x1, y0, y1;
            upk2(nn[p], n0, n1);
            upk2(jx[p], x0, x1);
            upk2(jy[p], y0, y1);
            // -1/tau = rcp(-(0.5 + 2^a))   (exp2-domain accumulators)
            u64 ntn = pk2(rcpa(-0.5f - ex2a(n0)), rcpa(-0.5f - ex2a(n1)));
            u64 ntx = pk2(rcpa(-0.5f - ex2a(x0)), rcpa(-0.5f - ex2a(x1)));
            u64 nty = pk2(rcpa(-0.5f - ex2a(y0)), rcpa(-0.5f - ex2a(y1)));

            // unhalved reconstruction: m1'..m8' = 2*m (exact)
            u64 m1 = fadd2(pq[p][0], pq[p][1]);   // 2*jx
            u64 m2 = fsub2(pq[p][0], pq[p][1]);   // 2*jy
            u64 m3 = fadd2(pq[p][2], pq[p][3]);   // 2*m3
            u64 m5 = fsub2(pq[p][2], pq[p][3]);   // 2*m5
            u64 m7 = fadd2(pq[p][4], pq[p][5]);   // 2*m7
            u64 m8 = fsub2(pq[p][4], pq[p][5]);   // 2*m8

            u64 r2 = fadd2(m0[p], m0[p]);         // 2*rho
            float r0, r1;
            upk2(r2, r0, r1);
            u64 rn = pk2(rcpa(-r0), rcpa(-r1));   // -1/(2rho)
            u64 jxr = fmul2(m1, rn);              // -jx/rho  (canonical scale)
            u64 jyr = fmul2(m2, rn);              // -jy/rho
            dm[p][0] = fadd2(m3, fmul2(m1, jxr));           // 2*(m3 - jx^2/rho)
            dm[p][1] = ffma2(c_two, m4[p], fmul2(m2, jxr)); // 2*(m4 - jxjy/rho)
            dm[p][2] = fadd2(m5, fmul2(m2, jyr));           // 2*(m5 - jy^2/rho)
            dm[p][3] = fmul2(m6[p], ntn);                   // 1x (-m6/tau_n)
            dm[p][4] = fmul2(m7, ntx);                      // 2*(-m7/tau_jx)
            dm[p][5] = fmul2(m8, nty);                      // 2*(-m8/tau_jy)
        }

        // ---- out_i = f_i + sum_c Mi6[i][c]*dm[c], structural zeros skipped:
        // Minv = W M^T D^-1 (moment rows orthogonal under D2Q9 weights), so
        // Mi6[i][c]==0 exactly where M[3+c][i]==0:
        //   c=1 (exy):  dirs 0-4 zero;  c=4 (gex): dirs 0,2,4 zero;
        //   c=5 (gey):  dirs 0,1,3 zero.
        #pragma unroll
        for (int i = 0; i < 9; ++i) {
            float4 v0 = __ldg(reinterpret_cast<const float4*>(f + i * N + idx));
            float4 v1 = __ldg(reinterpret_cast<const float4*>(f + i * N + idx + 4));
            u64 acc[NPAIR];
            acc[0] = pk2(v0.x, v0.y);
            acc[1] = pk2(v0.z, v0.w);
            acc[2] = pk2(v1.x, v1.y);
            acc[3] = pk2(v1.z, v1.w);
            #pragma unroll
            for (int c = 0; c < 6; ++c) {
                if (MASK[i] & (1 << c)) {
                    const float2 wc = cP.Mi6[i][c];
                    u64 wv = pk2(wc.x, wc.y);
                    #pragma unroll
                    for (int p = 0; p < NPAIR; ++p)
                        acc[p] = ffma2(wv, dm[p][c], acc[p]);
                }
            }
            float o0, o1, o2, o3, o4, o5, o6, o7;
            upk2(acc[0], o0, o1);
            upk2(acc[1], o2, o3);
            upk2(acc[2], o4, o5);
            upk2(acc[3], o6, o7);
            *reinterpret_cast<float4*>(out + i * N + idx)     = make_float4(o0, o1, o2, o3);
            *reinterpret_cast<float4*>(out + i * N + idx + 4) = make_float4(o4, o5, o6, o7);
        }
    }
}

extern "C" void kernel_launch(void* const* d_in, const int* in_sizes, int n_in,
                              void* d_out, int out_size)
{
    // input order: f, j_w1, j_b1, j_w2, j_b2, n_w1, n_b1, n_w2, n_b2, M, Minv
    const float* f = (const float*)d_in[0];
    prep_kernel<<<1, 96>>>((const float*)d_in[1], (const float*)d_in[2],
                           (const float*)d_in[3], (const float*)d_in[4],
                           (const float*)d_in[5], (const float*)d_in[6],
                           (const float*)d_in[7], (const float*)d_in[8],
                           (const float*)d_in[9], (const float*)d_in[10]);

    // Copy staged params into the __constant__ bank (graph-capturable D2D).
    void *dst = nullptr, *src = nullptr;
    cudaGetSymbolAddress(&dst, cP);
    cudaGetSymbolAddress(&src, g_p);
    cudaMemcpyAsync(dst, src, sizeof(Params), cudaMemcpyDeviceToDevice);

    int N = in_sizes[0] / 9;                       // 2048*2048 cells
    int ntile = (N + 128 * CELLS - 1) / (128 * CELLS);  // 1024 cells per tile
    int grid = 148 * 4;                            // one persistent wave
    if (grid > ntile) grid = ntile;
    lbm_kernel<<<grid, 128>>>(f, (float*)d_out, N, ntile);
}

// round 15
// speedup vs baseline: 1.1654x; 1.1654x over previous
#include <cuda_runtime.h>
#include <cstdint>

typedef unsigned long long u64;

// ---------------------------------------------------------------------------
// Per-hidden-unit interleaved record: 12 ulonglong2 (192B) = j record then n:
//  L0=(bias, w0) L1=(w4, w6) L2=(a1, a2) L3=(a3, b1) L4=(b2, b3) L5=(w2', 0)
// a_i=(w_k+w_k')/2, b_i=(w_k-w_k')/2 over FLIP pairs (1,2),(3,5),(7,8).
// straight = base + SUM a*p + SUM b*q ; flipped = base + SUM a*p - SUM b*q.
// w2'/output biases pre-scaled by log2(e)  (exp2-domain accumulators).
// Mi6 cols 0..2: x(-1/0.7) x0.5 ; cols 4,5: x0.5 ; col 3: x1
// (dm rows are produced at 2x scale from the unhalved pq basis; the 0.5 is
//  folded here. All scale factors are exact powers of two.)
// Weights live in __constant__ (warp-uniform h index -> LDC broadcast on the
// constant port; LSU/L1tex carries only f traffic).
// ---------------------------------------------------------------------------
struct __align__(16) Params {
    ulonglong2 W[24][12];
    float2 Mi6[9][6];
    float  jb2, nb2x2;
    float  pad[2];
};
__device__   Params g_p;   // staging (written by prep_kernel)
__constant__ Params cP;    // kernel-visible copy (memcpy'd in-stream)

__global__ void prep_kernel(const float* __restrict__ jw1, const float* __restrict__ jb1,
                            const float* __restrict__ jw2, const float* __restrict__ jb2,
                            const float* __restrict__ nw1, const float* __restrict__ nb1,
                            const float* __restrict__ nw2, const float* __restrict__ nb2,
                            const float* __restrict__ M,   const float* __restrict__ Mi)
{
    (void)M;
    const float LOG2E = 1.4426950408889634f;
    int t = threadIdx.x;
    if (t < 24) {
        int h = t;
        float2* wj = reinterpret_cast<float2*>(&g_p.W[h][0]);
        float2* wn = reinterpret_cast<float2*>(&g_p.W[h][6]);
        const float* J = jw1 + h * 9;
        const float* Nw = nw1 + h * 9;
        float v;
        v = jb1[h];               wj[0]  = make_float2(v, v);
        v = J[0];                 wj[1]  = make_float2(v, v);
        v = J[4];                 wj[2]  = make_float2(v, v);
        v = J[6];                 wj[3]  = make_float2(v, v);
        v = 0.5f * (J[1] + J[2]); wj[4]  = make_float2(v, v);  // a1
        v = 0.5f * (J[3] + J[5]); wj[5]  = make_float2(v, v);  // a2
        v = 0.5f * (J[7] + J[8]); wj[6]  = make_float2(v, v);  // a3
        v = 0.5f * (J[1] - J[2]); wj[7]  = make_float2(v, v);  // b1
        v = 0.5f * (J[3] - J[5]); wj[8]  = make_float2(v, v);  // b2
        v = 0.5f * (J[7] - J[8]); wj[9]  = make_float2(v, v);  // b3
        v = jw2[h] * LOG2E;       wj[10] = make_float2(v, v);
        wj[11] = make_float2(0.f, 0.f);
        v = nb1[h];                 wn[0]  = make_float2(v, v);
        v = Nw[0];                  wn[1]  = make_float2(v, v);
        v = Nw[4];                  wn[2]  = make_float2(v, v);
        v = Nw[6];                  wn[3]  = make_float2(v, v);
        v = 0.5f * (Nw[1] + Nw[2]); wn[4]  = make_float2(v, v);
        v = 0.5f * (Nw[3] + Nw[5]); wn[5]  = make_float2(v, v);
        v = 0.5f * (Nw[7] + Nw[8]); wn[6]  = make_float2(v, v);
        v = 0.5f * (Nw[1] - Nw[2]); wn[7]  = make_float2(v, v);
        v = 0.5f * (Nw[3] - Nw[5]); wn[8]  = make_float2(v, v);
        v = 0.5f * (Nw[7] - Nw[8]); wn[9]  = make_float2(v, v);
        v = nw2[h] * LOG2E;         wn[10] = make_float2(v, v);
        wn[11] = make_float2(0.f, 0.f);
    }
    if (t < 9)
        for (int c = 0; c < 6; ++c) {
            float v = Mi[t * 9 + 3 + c];
            if (c < 3) v *= -1.0f / 0.7f;   // fold tau=0.7 relaxation scale
            if (c != 3) v *= 0.5f;          // fold 2x scale of dm rows
            g_p.Mi6[t][c] = make_float2(v, v);
        }
    if (t == 0) { g_p.jb2 = jb2[0] * LOG2E; g_p.nb2x2 = 2.0f * nb2[0] * LOG2E; }
}

// ---------------------------------------------------------------------------
// f32x2 packed helpers
// ---------------------------------------------------------------------------
__device__ __forceinline__ u64 pk2(float lo, float hi) {
    u64 r; asm("mov.b64 %0, {%1, %2};" : "=l"(r) : "f"(lo), "f"(hi)); return r;
}
__device__ __forceinline__ void upk2(u64 v, float& lo, float& hi) {
    asm("mov.b64 {%0, %1}, %2;" : "=f"(lo), "=f"(hi) : "l"(v));
}
__device__ __forceinline__ u64 ffma2(u64 a, u64 b, u64 c) {
    u64 d; asm("fma.rn.f32x2 %0, %1, %2, %3;" : "=l"(d) : "l"(a), "l"(b), "l"(c)); return d;
}
__device__ __forceinline__ u64 fmul2(u64 a, u64 b) {
    u64 d; asm("mul.rn.f32x2 %0, %1, %2;" : "=l"(d) : "l"(a), "l"(b)); return d;
}
__device__ __forceinline__ u64 fadd2(u64 a, u64 b) {
    u64 d; asm("add.rn.f32x2 %0, %1, %2;" : "=l"(d) : "l"(a), "l"(b)); return d;
}
__device__ __forceinline__ u64 fsub2(u64 a, u64 b) {
    u64 d; asm("sub.rn.f32x2 %0, %1, %2;" : "=l"(d) : "l"(a), "l"(b)); return d;
}
__device__ __forceinline__ float rcpa(float x) {
    float r; asm("rcp.approx.f32 %0, %1;" : "=f"(r) : "f"(x)); return r;
}
__device__ __forceinline__ float ex2a(float x) {
    float r; asm("ex2.approx.f32 %0, %1;" : "=f"(r) : "f"(x)); return r;
}
__device__ __forceinline__ u64 relu2(u64 x) {
    float a, b; upk2(x, a, b);
    return pk2(fmaxf(a, 0.0f), fmaxf(b, 0.0f));
}

#define NPAIR 4   // packed cell-pairs per thread (8 cells)

// Sparse hardcoded moment transform -> m0, m4, m6 and FLIP-pair basis
// pq = {p1,q1,p2,q2,p3,q3}; all negations via sub.rn.f32x2 (no LOP).
__device__ __forceinline__ void moments(const u64 (&f)[9],
                                        u64& m0, u64& m4, u64& m6, u64* pq,
                                        u64 c_m2, u64 c_4, u64 c_m13)
{
    u64 s58 = fadd2(f[5], f[8]);
    u64 s67 = fadd2(f[6], f[7]);
    u64 d58 = fsub2(f[5], f[8]);
    u64 d67 = fsub2(f[6], f[7]);
    u64 t13 = fsub2(f[1], f[3]);
    u64 t24 = fsub2(f[2], f[4]);
    u64 s13 = fadd2(f[1], f[3]);
    u64 s24 = fadd2(f[2], f[4]);
    u64 u = fsub2(s58, s67);               // f5-f6-f7+f8
    u64 v = fadd2(d58, d67);               // f5+f6-f7-f8
    u64 Q = fadd2(s58, s67);
    u64 P = fadd2(s13, s24);
    m0 = fadd2(f[0], fadd2(P, Q));
    m4 = fsub2(d58, d67);                  // f5-f6+f7-f8
    m6 = ffma2(P, c_m2, ffma2(Q, c_4, f[0]));
    u64 m1 = fadd2(t13, u);
    u64 m2 = fadd2(t24, v);
    u64 m3 = ffma2(m0, c_m13, fadd2(s13, Q));
    u64 m5 = ffma2(m0, c_m13, fadd2(s24, Q));
    u64 m7 = ffma2(t13, c_m2, fmul2(u, c_4));
    u64 m8 = ffma2(t24, c_m2, fmul2(v, c_4));
    pq[0] = fadd2(m1, m2);
    pq[1] = fsub2(m1, m2);
    pq[2] = fadd2(m3, m5);
    pq[3] = fsub2(m3, m5);
    pq[4] = fadd2(m7, m8);
    pq[5] = fsub2(m7, m8);
}

__global__ __launch_bounds__(128, 4) void lbm_kernel(const float* __restrict__ f,
                                                     float* __restrict__ out, int N)
{
    int idx = (blockIdx.x * blockDim.x + threadIdx.x) * (NPAIR * 2);
    if (idx >= N) return;

    const u64 c_m2  = pk2(-2.0f, -2.0f);
    const u64 c_4   = pk2(4.0f, 4.0f);
    const u64 c_m13 = pk2(-1.0f / 3.0f, -1.0f / 3.0f);
    const u64 c_two = pk2(2.0f, 2.0f);

    // ---- load f, compute moment basis; f regs die here (reloaded at output)
    u64 m0[NPAIR], m4[NPAIR], m6[NPAIR], pq[NPAIR][6];
    {
        u64 fv[NPAIR][9];
        #pragma unroll
        for (int i = 0; i < 9; ++i) {
            float4 v0 = *reinterpret_cast<const float4*>(f + i * N + idx);
            float4 v1 = *reinterpret_cast<const float4*>(f + i * N + idx + 4);
            fv[0][i] = pk2(v0.x, v0.y);
            fv[1][i] = pk2(v0.z, v0.w);
            fv[2][i] = pk2(v1.x, v1.y);
            fv[3][i] = pk2(v1.z, v1.w);
        }
        #pragma unroll
        for (int p = 0; p < NPAIR; ++p)
            moments(fv[p], m0[p], m4[p], m6[p], pq[p], c_m2, c_4, c_m13);
    }

    // ---- fused j+n MLPs over 24 hidden units, weights via constant port
    u64 jx[NPAIR], jy[NPAIR], nn[NPAIR];
    {
        u64 jb = pk2(cP.jb2, cP.jb2);
        u64 nb = pk2(cP.nb2x2, cP.nb2x2);
        #pragma unroll
        for (int p = 0; p < NPAIR; ++p) { jx[p] = jb; jy[p] = jb; nn[p] = nb; }
    }

    for (int h = 0; h < 24; ++h) {
        // ---- j network
        {
            ulonglong2 L0 = cP.W[h][0], L1 = cP.W[h][1], L2 = cP.W[h][2];
            ulonglong2 L3 = cP.W[h][3], L4 = cP.W[h][4], L5 = cP.W[h][5];
            #pragma unroll
            for (int p = 0; p < NPAIR; ++p) {
                u64 t = ffma2(L0.y, m0[p], L0.x);
                t = ffma2(L1.x, m4[p], t);
                t = ffma2(L1.y, m6[p], t);
                t = ffma2(L2.x, pq[p][0], t);
                t = ffma2(L2.y, pq[p][2], t);
                t = ffma2(L3.x, pq[p][4], t);
                u64 u = fmul2(L3.y, pq[p][1]);
                u = ffma2(L4.x, pq[p][3], u);
                u = ffma2(L4.y, pq[p][5], u);
                u64 s = fadd2(t, u);
                u64 fl = fsub2(t, u);
                jx[p] = ffma2(L5.x, relu2(s), jx[p]);
                jy[p] = ffma2(L5.x, relu2(fl), jy[p]);
            }
        }
        // ---- n network
        {
            ulonglong2 L0 = cP.W[h][6], L1 = cP.W[h][7], L2 = cP.W[h][8];
            ulonglong2 L3 = cP.W[h][9], L4 = cP.W[h][10], L5 = cP.W[h][11];
            #pragma unroll
            for (int p = 0; p < NPAIR; ++p) {
                u64 t = ffma2(L0.y, m0[p], L0.x);
                t = ffma2(L1.x, m4[p], t);
                t = ffma2(L1.y, m6[p], t);
                t = ffma2(L2.x, pq[p][0], t);
                t = ffma2(L2.y, pq[p][2], t);
                t = ffma2(L3.x, pq[p][4], t);
                u64 u = fmul2(L3.y, pq[p][1]);
                u = ffma2(L4.x, pq[p][3], u);
                u = ffma2(L4.y, pq[p][5], u);
                u64 s = fadd2(t, u);
                u64 fl = fsub2(t, u);
                nn[p] = ffma2(L5.x, fadd2(relu2(s), relu2(fl)), nn[p]);
            }
        }
    }

    // ---- per-pair relax factors and dm rows (2x scale; 0.5 folded in Mi6)
    u64 dm[NPAIR][6];
    #pragma unroll
    for (int p = 0; p < NPAIR; ++p) {
        float n0, n1, x0, x1, y0, y1;
        upk2(nn[p], n0, n1);
        upk2(jx[p], x0, x1);
        upk2(jy[p], y0, y1);
        // -1/tau = rcp(-(0.5 + 2^a))   (exp2-domain accumulators)
        u64 ntn = pk2(rcpa(-0.5f - ex2a(n0)), rcpa(-0.5f - ex2a(n1)));
        u64 ntx = pk2(rcpa(-0.5f - ex2a(x0)), rcpa(-0.5f - ex2a(x1)));
        u64 nty = pk2(rcpa(-0.5f - ex2a(y0)), rcpa(-0.5f - ex2a(y1)));

        // unhalved reconstruction: m1'..m8' = 2*m (exact)
        u64 m1 = fadd2(pq[p][0], pq[p][1]);   // 2*jx
        u64 m2 = fsub2(pq[p][0], pq[p][1]);   // 2*jy
        u64 m3 = fadd2(pq[p][2], pq[p][3]);   // 2*m3
        u64 m5 = fsub2(pq[p][2], pq[p][3]);   // 2*m5
        u64 m7 = fadd2(pq[p][4], pq[p][5]);   // 2*m7
        u64 m8 = fsub2(pq[p][4], pq[p][5]);   // 2*m8

        u64 r2 = fadd2(m0[p], m0[p]);         // 2*rho
        float r0, r1;
        upk2(r2, r0, r1);
        u64 rn = pk2(rcpa(-r0), rcpa(-r1));   // -1/(2rho)
        u64 jxr = fmul2(m1, rn);              // -jx/rho  (canonical scale)
        u64 jyr = fmul2(m2, rn);              // -jy/rho
        dm[p][0] = fadd2(m3, fmul2(m1, jxr));           // 2*(m3 - jx^2/rho)
        dm[p][1] = ffma2(c_two, m4[p], fmul2(m2, jxr)); // 2*(m4 - jxjy/rho)
        dm[p][2] = fadd2(m5, fmul2(m2, jyr));           // 2*(m5 - jy^2/rho)
        dm[p][3] = fmul2(m6[p], ntn);                   // 1x (-m6/tau_n)
        dm[p][4] = fmul2(m7, ntx);                      // 2*(-m7/tau_jx)
        dm[p][5] = fmul2(m8, nty);                      // 2*(-m8/tau_jy)
    }

    // ---- out_i = f_i + sum_c Mi6[i][c]*dm[c], structural zeros skipped:
    // Minv = W M^T D^-1 (moment rows orthogonal under D2Q9 weights), so
    // Mi6[i][c]==0 exactly where M[3+c][i]==0:
    //   c=1 (exy):  dirs 0-4 zero;  c=4 (gex): dirs 0,2,4 zero;
    //   c=5 (gey):  dirs 0,1,3 zero.
    const int MASK[9] = {0x0D, 0x1D, 0x2D, 0x1D, 0x2D, 0x3F, 0x3F, 0x3F, 0x3F};
    #pragma unroll
    for (int i = 0; i < 9; ++i) {
        float4 v0 = __ldg(reinterpret_cast<const float4*>(f + i * N + idx));
        float4 v1 = __ldg(reinterpret_cast<const float4*>(f + i * N + idx + 4));
        u64 acc[NPAIR];
        acc[0] = pk2(v0.x, v0.y);
        acc[1] = pk2(v0.z, v0.w);
        acc[2] = pk2(v1.x, v1.y);
        acc[3] = pk2(v1.z, v1.w);
        #pragma unroll
        for (int c = 0; c < 6; ++c) {
            if (MASK[i] & (1 << c)) {
                const float2 wc = cP.Mi6[i][c];
                u64 wv = pk2(wc.x, wc.y);
                #pragma unroll
                for (int p = 0; p < NPAIR; ++p)
                    acc[p] = ffma2(wv, dm[p][c], acc[p]);
            }
        }
        float o0, o1, o2, o3, o4, o5, o6, o7;
        upk2(acc[0], o0, o1);
        upk2(acc[1], o2, o3);
        upk2(acc[2], o4, o5);
        upk2(acc[3], o6, o7);
        *reinterpret_cast<float4*>(out + i * N + idx)     = make_float4(o0, o1, o2, o3);
        *reinterpret_cast<float4*>(out + i * N + idx + 4) = make_float4(o4, o5, o6, o7);
    }
}

extern "C" void kernel_launch(void* const* d_in, const int* in_sizes, int n_in,
                              void* d_out, int out_size)
{
    // input order: f, j_w1, j_b1, j_w2, j_b2, n_w1, n_b1, n_w2, n_b2, M, Minv
    const float* f = (const float*)d_in[0];
    prep_kernel<<<1, 96>>>((const float*)d_in[1], (const float*)d_in[2],
                           (const float*)d_in[3], (const float*)d_in[4],
                           (const float*)d_in[5], (const float*)d_in[6],
                           (const float*)d_in[7], (const float*)d_in[8],
                           (const float*)d_in[9], (const float*)d_in[10]);

    // Copy staged params into the __constant__ bank (graph-capturable D2D).
    void *dst = nullptr, *src = nullptr;
    cudaGetSymbolAddress(&dst, cP);
    cudaGetSymbolAddress(&src, g_p);
    cudaMemcpyAsync(dst, src, sizeof(Params), cudaMemcpyDeviceToDevice);

    int N = in_sizes[0] / 9;                     // 2048*2048 cells
    int threads = (N + NPAIR * 2 - 1) / (NPAIR * 2);  // 8 cells per thread
    int block = 128;
    int grid = (threads + block - 1) / block;
    lbm_kernel<<<grid, block>>>(f, (float*)d_out, N);
}

// round 16
// speedup vs baseline: 1.1675x; 1.0018x over previous
#include <cuda_runtime.h>
#include <cstdint>

typedef unsigned long long u64;

// ---------------------------------------------------------------------------
// Per-hidden-unit interleaved record: 12 ulonglong2 (192B) = j record then n:
//  L0=(bias, w0) L1=(w4, w6) L2=(a1, a2) L3=(a3, b1) L4=(b2, b3) L5=(w2', 0)
// a_i=(w_k+w_k')/2, b_i=(w_k-w_k')/2 over FLIP pairs (1,2),(3,5),(7,8).
// straight = base + SUM a*p + SUM b*q ; flipped = base + SUM a*p - SUM b*q.
// w2'/output biases pre-scaled by log2(e)  (exp2-domain accumulators).
// Mi6 cols 0..2: x(-1/0.7) x0.5 ; cols 4,5: x0.5 ; col 3: x1
// (dm rows are produced at 2x scale from the unhalved pq basis; the 0.5 is
//  folded here. All scale factors are exact powers of two.)
// Weights live in __constant__ (warp-uniform h index -> LDC broadcast on the
// constant port; LSU/L1tex carries only f traffic).
// n-network uses relu(t+u)+relu(t-u) == relu(t + max(t,|u|))  (exact).
// ---------------------------------------------------------------------------
struct __align__(16) Params {
    ulonglong2 W[24][12];
    float2 Mi6[9][6];
    float  jb2, nb2x2;
    float  pad[2];
};
__device__   Params g_p;   // staging (written by prep_kernel)
__constant__ Params cP;    // kernel-visible copy (memcpy'd in-stream)

__global__ void prep_kernel(const float* __restrict__ jw1, const float* __restrict__ jb1,
                            const float* __restrict__ jw2, const float* __restrict__ jb2,
                            const float* __restrict__ nw1, const float* __restrict__ nb1,
                            const float* __restrict__ nw2, const float* __restrict__ nb2,
                            const float* __restrict__ M,   const float* __restrict__ Mi)
{
    (void)M;
    const float LOG2E = 1.4426950408889634f;
    int t = threadIdx.x;
    if (t < 24) {
        int h = t;
        float2* wj = reinterpret_cast<float2*>(&g_p.W[h][0]);
        float2* wn = reinterpret_cast<float2*>(&g_p.W[h][6]);
        const float* J = jw1 + h * 9;
        const float* Nw = nw1 + h * 9;
        float v;
        v = jb1[h];               wj[0]  = make_float2(v, v);
        v = J[0];                 wj[1]  = make_float2(v, v);
        v = J[4];                 wj[2]  = make_float2(v, v);
        v = J[6];                 wj[3]  = make_float2(v, v);
        v = 0.5f * (J[1] + J[2]); wj[4]  = make_float2(v, v);  // a1
        v = 0.5f * (J[3] + J[5]); wj[5]  = make_float2(v, v);  // a2
        v = 0.5f * (J[7] + J[8]); wj[6]  = make_float2(v, v);  // a3
        v = 0.5f * (J[1] - J[2]); wj[7]  = make_float2(v, v);  // b1
        v = 0.5f * (J[3] - J[5]); wj[8]  = make_float2(v, v);  // b2
        v = 0.5f * (J[7] - J[8]); wj[9]  = make_float2(v, v);  // b3
        v = jw2[h] * LOG2E;       wj[10] = make_float2(v, v);
        wj[11] = make_float2(0.f, 0.f);
        v = nb1[h];                 wn[0]  = make_float2(v, v);
        v = Nw[0];                  wn[1]  = make_float2(v, v);
        v = Nw[4];                  wn[2]  = make_float2(v, v);
        v = Nw[6];                  wn[3]  = make_float2(v, v);
        v = 0.5f * (Nw[1] + Nw[2]); wn[4]  = make_float2(v, v);
        v = 0.5f * (Nw[3] + Nw[5]); wn[5]  = make_float2(v, v);
        v = 0.5f * (Nw[7] + Nw[8]); wn[6]  = make_float2(v, v);
        v = 0.5f * (Nw[1] - Nw[2]); wn[7]  = make_float2(v, v);
        v = 0.5f * (Nw[3] - Nw[5]); wn[8]  = make_float2(v, v);
        v = 0.5f * (Nw[7] - Nw[8]); wn[9]  = make_float2(v, v);
        v = nw2[h] * LOG2E;         wn[10] = make_float2(v, v);
        wn[11] = make_float2(0.f, 0.f);
    }
    if (t < 9)
        for (int c = 0; c < 6; ++c) {
            float v = Mi[t * 9 + 3 + c];
            if (c < 3) v *= -1.0f / 0.7f;   // fold tau=0.7 relaxation scale
            if (c != 3) v *= 0.5f;          // fold 2x scale of dm rows
            g_p.Mi6[t][c] = make_float2(v, v);
        }
    if (t == 0) { g_p.jb2 = jb2[0] * LOG2E; g_p.nb2x2 = 2.0f * nb2[0] * LOG2E; }
}

// ---------------------------------------------------------------------------
// f32x2 packed helpers
// ---------------------------------------------------------------------------
__device__ __forceinline__ u64 pk2(float lo, float hi) {
    u64 r; asm("mov.b64 %0, {%1, %2};" : "=l"(r) : "f"(lo), "f"(hi)); return r;
}
__device__ __forceinline__ void upk2(u64 v, float& lo, float& hi) {
    asm("mov.b64 {%0, %1}, %2;" : "=f"(lo), "=f"(hi) : "l"(v));
}
__device__ __forceinline__ u64 ffma2(u64 a, u64 b, u64 c) {
    u64 d; asm("fma.rn.f32x2 %0, %1, %2, %3;" : "=l"(d) : "l"(a), "l"(b), "l"(c)); return d;
}
__device__ __forceinline__ u64 fmul2(u64 a, u64 b) {
    u64 d; asm("mul.rn.f32x2 %0, %1, %2;" : "=l"(d) : "l"(a), "l"(b)); return d;
}
__device__ __forceinline__ u64 fadd2(u64 a, u64 b) {
    u64 d; asm("add.rn.f32x2 %0, %1, %2;" : "=l"(d) : "l"(a), "l"(b)); return d;
}
__device__ __forceinline__ u64 fsub2(u64 a, u64 b) {
    u64 d; asm("sub.rn.f32x2 %0, %1, %2;" : "=l"(d) : "l"(a), "l"(b)); return d;
}
__device__ __forceinline__ float rcpa(float x) {
    float r; asm("rcp.approx.f32 %0, %1;" : "=f"(r) : "f"(x)); return r;
}
__device__ __forceinline__ float ex2a(float x) {
    float r; asm("ex2.approx.f32 %0, %1;" : "=f"(r) : "f"(x)); return r;
}
__device__ __forceinline__ u64 relu2(u64 x) {
    float a, b; upk2(x, a, b);
    return pk2(fmaxf(a, 0.0f), fmaxf(b, 0.0f));
}

#define NPAIR 4   // packed cell-pairs per thread (8 cells)

// Sparse hardcoded moment transform -> m0, m4, m6 and FLIP-pair basis
// pq = {p1,q1,p2,q2,p3,q3}; all negations via sub.rn.f32x2 (no LOP).
__device__ __forceinline__ void moments(const u64 (&f)[9],
                                        u64& m0, u64& m4, u64& m6, u64* pq,
                                        u64 c_m2, u64 c_4, u64 c_m13)
{
    u64 s58 = fadd2(f[5], f[8]);
    u64 s67 = fadd2(f[6], f[7]);
    u64 d58 = fsub2(f[5], f[8]);
    u64 d67 = fsub2(f[6], f[7]);
    u64 t13 = fsub2(f[1], f[3]);
    u64 t24 = fsub2(f[2], f[4]);
    u64 s13 = fadd2(f[1], f[3]);
    u64 s24 = fadd2(f[2], f[4]);
    u64 u = fsub2(s58, s67);               // f5-f6-f7+f8
    u64 v = fadd2(d58, d67);               // f5+f6-f7-f8
    u64 Q = fadd2(s58, s67);
    u64 P = fadd2(s13, s24);
    m0 = fadd2(f[0], fadd2(P, Q));
    m4 = fsub2(d58, d67);                  // f5-f6+f7-f8
    m6 = ffma2(P, c_m2, ffma2(Q, c_4, f[0]));
    u64 m1 = fadd2(t13, u);
    u64 m2 = fadd2(t24, v);
    u64 m3 = ffma2(m0, c_m13, fadd2(s13, Q));
    u64 m5 = ffma2(m0, c_m13, fadd2(s24, Q));
    u64 m7 = ffma2(t13, c_m2, fmul2(u, c_4));
    u64 m8 = ffma2(t24, c_m2, fmul2(v, c_4));
    pq[0] = fadd2(m1, m2);
    pq[1] = fsub2(m1, m2);
    pq[2] = fadd2(m3, m5);
    pq[3] = fsub2(m3, m5);
    pq[4] = fadd2(m7, m8);
    pq[5] = fsub2(m7, m8);
}

__global__ __launch_bounds__(128, 4) void lbm_kernel(const float* __restrict__ f,
                                                     float* __restrict__ out, int N)
{
    int idx = (blockIdx.x * blockDim.x + threadIdx.x) * (NPAIR * 2);
    if (idx >= N) return;

    const u64 c_m2  = pk2(-2.0f, -2.0f);
    const u64 c_4   = pk2(4.0f, 4.0f);
    const u64 c_m13 = pk2(-1.0f / 3.0f, -1.0f / 3.0f);
    const u64 c_two = pk2(2.0f, 2.0f);

    // ---- load f, compute moment basis; f regs die here (reloaded at output)
    u64 m0[NPAIR], m4[NPAIR], m6[NPAIR], pq[NPAIR][6];
    {
        u64 fv[NPAIR][9];
        #pragma unroll
        for (int i = 0; i < 9; ++i) {
            float4 v0 = *reinterpret_cast<const float4*>(f + i * N + idx);
            float4 v1 = *reinterpret_cast<const float4*>(f + i * N + idx + 4);
            fv[0][i] = pk2(v0.x, v0.y);
            fv[1][i] = pk2(v0.z, v0.w);
            fv[2][i] = pk2(v1.x, v1.y);
            fv[3][i] = pk2(v1.z, v1.w);
        }
        #pragma unroll
        for (int p = 0; p < NPAIR; ++p)
            moments(fv[p], m0[p], m4[p], m6[p], pq[p], c_m2, c_4, c_m13);
    }

    // ---- fused j+n MLPs over 24 hidden units, weights via constant port
    u64 jx[NPAIR], jy[NPAIR], nn[NPAIR];
    {
        u64 jb = pk2(cP.jb2, cP.jb2);
        u64 nb = pk2(cP.nb2x2, cP.nb2x2);
        #pragma unroll
        for (int p = 0; p < NPAIR; ++p) { jx[p] = jb; jy[p] = jb; nn[p] = nb; }
    }

    for (int h = 0; h < 24; ++h) {
        // ---- j network
        {
            ulonglong2 L0 = cP.W[h][0], L1 = cP.W[h][1], L2 = cP.W[h][2];
            ulonglong2 L3 = cP.W[h][3], L4 = cP.W[h][4], L5 = cP.W[h][5];
            #pragma unroll
            for (int p = 0; p < NPAIR; ++p) {
                u64 t = ffma2(L0.y, m0[p], L0.x);
                t = ffma2(L1.x, m4[p], t);
                t = ffma2(L1.y, m6[p], t);
                t = ffma2(L2.x, pq[p][0], t);
                t = ffma2(L2.y, pq[p][2], t);
                t = ffma2(L3.x, pq[p][4], t);
                u64 u = fmul2(L3.y, pq[p][1]);
                u = ffma2(L4.x, pq[p][3], u);
                u = ffma2(L4.y, pq[p][5], u);
                u64 s = fadd2(t, u);
                u64 fl = fsub2(t, u);
                jx[p] = ffma2(L5.x, relu2(s), jx[p]);
                jy[p] = ffma2(L5.x, relu2(fl), jy[p]);
            }
        }
        // ---- n network: relu(t+u)+relu(t-u) == relu(t + max(t,|u|))  (exact)
        {
            ulonglong2 L0 = cP.W[h][6], L1 = cP.W[h][7], L2 = cP.W[h][8];
            ulonglong2 L3 = cP.W[h][9], L4 = cP.W[h][10], L5 = cP.W[h][11];
            #pragma unroll
            for (int p = 0; p < NPAIR; ++p) {
                u64 t = ffma2(L0.y, m0[p], L0.x);
                t = ffma2(L1.x, m4[p], t);
                t = ffma2(L1.y, m6[p], t);
                t = ffma2(L2.x, pq[p][0], t);
                t = ffma2(L2.y, pq[p][2], t);
                t = ffma2(L3.x, pq[p][4], t);
                u64 u = fmul2(L3.y, pq[p][1]);
                u = ffma2(L4.x, pq[p][3], u);
                u = ffma2(L4.y, pq[p][5], u);
                float t0, t1, u0, u1;
                upk2(t, t0, t1);
                upk2(u, u0, u1);
                float r0 = fmaxf(t0 + fmaxf(t0, fabsf(u0)), 0.0f);
                float r1 = fmaxf(t1 + fmaxf(t1, fabsf(u1)), 0.0f);
                nn[p] = ffma2(L5.x, pk2(r0, r1), nn[p]);
            }
        }
    }

    // ---- per-pair relax factors and dm rows (2x scale; 0.5 folded in Mi6)
    u64 dm[NPAIR][6];
    #pragma unroll
    for (int p = 0; p < NPAIR; ++p) {
        float n0, n1, x0, x1, y0, y1;
        upk2(nn[p], n0, n1);
        upk2(jx[p], x0, x1);
        upk2(jy[p], y0, y1);
        // -1/tau = rcp(-(0.5 + 2^a))   (exp2-domain accumulators)
        u64 ntn = pk2(rcpa(-0.5f - ex2a(n0)), rcpa(-0.5f - ex2a(n1)));
        u64 ntx = pk2(rcpa(-0.5f - ex2a(x0)), rcpa(-0.5f - ex2a(x1)));
        u64 nty = pk2(rcpa(-0.5f - ex2a(y0)), rcpa(-0.5f - ex2a(y1)));

        // unhalved reconstruction: m1'..m8' = 2*m (exact)
        u64 m1 = fadd2(pq[p][0], pq[p][1]);   // 2*jx
        u64 m2 = fsub2(pq[p][0], pq[p][1]);   // 2*jy
        u64 m3 = fadd2(pq[p][2], pq[p][3]);   // 2*m3
        u64 m5 = fsub2(pq[p][2], pq[p][3]);   // 2*m5
        u64 m7 = fadd2(pq[p][4], pq[p][5]);   // 2*m7
        u64 m8 = fsub2(pq[p][4], pq[p][5]);   // 2*m8

        u64 r2 = fadd2(m0[p], m0[p]);         // 2*rho
        float r0, r1;
        upk2(r2, r0, r1);
        u64 rn = pk2(rcpa(-r0), rcpa(-r1));   // -1/(2rho)
        u64 jxr = fmul2(m1, rn);              // -jx/rho  (canonical scale)
        u64 jyr = fmul2(m2, rn);              // -jy/rho
        dm[p][0] = fadd2(m3, fmul2(m1, jxr));           // 2*(m3 - jx^2/rho)
        dm[p][1] = ffma2(c_two, m4[p], fmul2(m2, jxr)); // 2*(m4 - jxjy/rho)
        dm[p][2] = fadd2(m5, fmul2(m2, jyr));           // 2*(m5 - jy^2/rho)
        dm[p][3] = fmul2(m6[p], ntn);                   // 1x (-m6/tau_n)
        dm[p][4] = fmul2(m7, ntx);                      // 2*(-m7/tau_jx)
        dm[p][5] = fmul2(m8, nty);                      // 2*(-m8/tau_jy)
    }

    // ---- out_i = f_i + sum_c Mi6[i][c]*dm[c], structural zeros skipped:
    // Minv = W M^T D^-1 (moment rows orthogonal under D2Q9 weights), so
    // Mi6[i][c]==0 exactly where M[3+c][i]==0:
    //   c=1 (exy):  dirs 0-4 zero;  c=4 (gex): dirs 0,2,4 zero;
    //   c=5 (gey):  dirs 0,1,3 zero.
    const int MASK[9] = {0x0D, 0x1D, 0x2D, 0x1D, 0x2D, 0x3F, 0x3F, 0x3F, 0x3F};
    #pragma unroll
    for (int i = 0; i < 9; ++i) {
        float4 v0 = __ldg(reinterpret_cast<const float4*>(f + i * N + idx));
        float4 v1 = __ldg(reinterpret_cast<const float4*>(f + i * N + idx + 4));
        u64 acc[NPAIR];
        acc[0] = pk2(v0.x, v0.y);
        acc[1] = pk2(v0.z, v0.w);
        acc[2] = pk2(v1.x, v1.y);
        acc[3] = pk2(v1.z, v1.w);
        #pragma unroll
        for (int c = 0; c < 6; ++c) {
            if (MASK[i] & (1 << c)) {
                const float2 wc = cP.Mi6[i][c];
                u64 wv = pk2(wc.x, wc.y);
                #pragma unroll
                for (int p = 0; p < NPAIR; ++p)
                    acc[p] = ffma2(wv, dm[p][c], acc[p]);
            }
        }
        float o0, o1, o2, o3, o4, o5, o6, o7;
        upk2(acc[0], o0, o1);
        upk2(acc[1], o2, o3);
        upk2(acc[2], o4, o5);
        upk2(acc[3], o6, o7);
        *reinterpret_cast<float4*>(out + i * N + idx)     = make_float4(o0, o1, o2, o3);
        *reinterpret_cast<float4*>(out + i * N + idx + 4) = make_float4(o4, o5, o6, o7);
    }
}

extern "C" void kernel_launch(void* const* d_in, const int* in_sizes, int n_in,
                              void* d_out, int out_size)
{
    // input order: f, j_w1, j_b1, j_w2, j_b2, n_w1, n_b1, n_w2, n_b2, M, Minv
    const float* f = (const float*)d_in[0];
    prep_kernel<<<1, 96>>>((const float*)d_in[1], (const float*)d_in[2],
                           (const float*)d_in[3], (const float*)d_in[4],
                           (const float*)d_in[5], (const float*)d_in[6],
                           (const float*)d_in[7], (const float*)d_in[8],
                           (const float*)d_in[9], (const float*)d_in[10]);

    // Copy staged params into the __constant__ bank (graph-capturable D2D).
    void *dst = nullptr, *src = nullptr;
    cudaGetSymbolAddress(&dst, cP);
    cudaGetSymbolAddress(&src, g_p);
    cudaMemcpyAsync(dst, src, sizeof(Params), cudaMemcpyDeviceToDevice);

    int N = in_sizes[0] / 9;                     // 2048*2048 cells
    int threads = (N + NPAIR * 2 - 1) / (NPAIR * 2);  // 8 cells per thread
    int block = 128;
    int grid = (threads + block - 1) / block;
    lbm_kernel<<<grid, block>>>(f, (float*)d_out, N);
}